// round 7
// baseline (speedup 1.0000x reference)
#include <cuda_runtime.h>
#include <cuda_fp16.h>
#include <cstdint>

#define N_CLASSES 64
#define DIM 128
#define QT 256            // queries per block in MMA kernel

// ---------------- device scratch ----------------
__device__ float g_psum[N_CLASSES * DIM];
__device__ float g_pcnt[N_CLASSES];
__device__ float g_pnorm[N_CLASSES];
__device__ int   g_lbl_is64;
// prototypes as fp16, pre-packed in mma.m16n8k16 B-FRAGMENT order:
// [8 ksteps][8 ntiles][32 lanes][2 regs][2 halves]
__device__ unsigned short g_pBf[8192];

// ---------------- helpers ----------------
__device__ __forceinline__ uint32_t smem_u32(const void* p) {
    uint32_t a;
    asm("{ .reg .u64 t; cvta.to.shared.u64 t, %1; cvt.u32.u64 %0, t; }"
        : "=r"(a) : "l"(p));
    return a;
}
__device__ __forceinline__ uint32_t swz(uint32_t off) { return off ^ ((off >> 3) & 0x70); }

__device__ __forceinline__ void ldmatrix_x4(uint32_t* r, uint32_t addr) {
    asm volatile("ldmatrix.sync.aligned.m8n8.x4.shared.b16 {%0,%1,%2,%3}, [%4];"
                 : "=r"(r[0]), "=r"(r[1]), "=r"(r[2]), "=r"(r[3]) : "r"(addr));
}
__device__ __forceinline__ void mma_f16(float* d, const uint32_t* a, uint32_t b0, uint32_t b1) {
    asm volatile(
        "mma.sync.aligned.m16n8k16.row.col.f32.f16.f16.f32 "
        "{%0,%1,%2,%3}, {%4,%5,%6,%7}, {%8,%9}, {%0,%1,%2,%3};"
        : "+f"(d[0]), "+f"(d[1]), "+f"(d[2]), "+f"(d[3])
        : "r"(a[0]), "r"(a[1]), "r"(a[2]), "r"(a[3]), "r"(b0), "r"(b1));
}

// ---------------- smem layout for k_mma (bytes) ----------------
#define SM_QN     0                       // 256 x 4 = 1024
#define SM_PN     1024                    // 64 x 4
#define SM_A      2048                    // 2 chunks x 256 rows x 128B = 65536
#define SM_B      (SM_A + 65536)          // 16384 (B fragments)
#define SM_TOTAL  (SM_B + 16384)          // 83968 -> 2 CTA/SM
#define OUT_STRIDE 68                     // floats; staging 256*68*4=69632 <= 81920

// ================= kernel 0: zero + label dtype detect =================
__global__ void k_zero(const int* __restrict__ lbl32) {
    int t = threadIdx.x;
    for (int i = t; i < N_CLASSES * DIM; i += 256) g_psum[i] = 0.0f;
    if (t < N_CLASSES) g_pcnt[t] = 0.0f;

    __shared__ int s_or[256];
    s_or[t] = lbl32[2 * t + 1];
    __syncthreads();
    for (int s = 128; s > 0; s >>= 1) {
        if (t < s) s_or[t] |= s_or[t + s];
        __syncthreads();
    }
    if (t == 0) g_lbl_is64 = (s_or[0] == 0) ? 1 : 0;
}

// ================= kernel 1: class-sum accumulate (NO atomics in loop) ====
// 8 warps/block; warp (g = w&3, p = w>>2) owns a PRIVATE slab [64][32] for
// dim-group g (dims 32g..32g+31) over rows of parity p. Plain smem RMW,
// conflict-free (bank = lane). One global-atomic flush per block.
#define ACC_BLOCKS 128
#define ACC_ROWS   512   // rows per block (65536/128)
__global__ __launch_bounds__(256) void k_accum(const float* __restrict__ emb,
                                               const int* __restrict__ lbl32,
                                               int nrows) {
    extern __shared__ float sh[];
    float* s_slab = sh;                          // 8 x 2048 floats = 64 KB
    float* s_cnt  = sh + 8 * 2048;               // 8 x 64
    int*   s_lbl  = (int*)(s_cnt + 8 * 64);      // 512

    const int tid = threadIdx.x;
    const int w = tid >> 5, lane = tid & 31;
    const int g = w & 3, p = w >> 2;
    const int shift = g_lbl_is64;

    for (int i = tid; i < 8 * 2048; i += 256) s_slab[i] = 0.0f;
    for (int i = tid; i < 8 * 64; i += 256) s_cnt[i] = 0.0f;

    const int r0 = blockIdx.x * ACC_ROWS;
    const int nr = min(ACC_ROWS, nrows - r0);
    for (int i = tid; i < nr; i += 256) s_lbl[i] = lbl32[(r0 + i) << shift];
    __syncthreads();

    float* slab = s_slab + w * 2048;
    float* cnt  = s_cnt + w * 64;
    for (int i = p; i < nr; i += 2) {
        int c = s_lbl[i];                                     // warp-uniform
        float v = emb[(size_t)(r0 + i) * DIM + g * 32 + lane]; // coalesced 128B
        slab[c * 32 + lane] += v;                              // private RMW
        if (lane == 0 && g == 0) cnt[c] += 1.0f;
    }
    __syncthreads();

    // flush: sum the two parities, one global atomic per element
    for (int i = tid; i < N_CLASSES * DIM; i += 256) {
        int c = i >> 7, d = i & 127;
        int gg = d >> 5, l = d & 31;
        float v = s_slab[gg * 2048 + c * 32 + l] + s_slab[(gg + 4) * 2048 + c * 32 + l];
        if (v != 0.0f) atomicAdd(&g_psum[i], v);
    }
    if (tid < N_CLASSES) {
        float cv = s_cnt[tid] + s_cnt[4 * 64 + tid];
        if (cv != 0.0f) atomicAdd(&g_pcnt[tid], cv);
    }
}

// ================= kernel 2: finalize protos -> fp16 B fragments + pnorm ===
// One block per class c (64 blocks, 128 threads = dims).
__global__ void k_final() {
    const int c = blockIdx.x;
    const int d = threadIdx.x;
    float cn = fmaxf(g_pcnt[c], 1.0f);
    float v = g_psum[c * DIM + d] / cn;

    __half hv = __float2half_rn(v);
    float vrec = __half2float(hv);

    int nt = c >> 3;
    int ks = d >> 4;
    int kp = d & 15;
    int lane = 4 * (c & 7) + ((kp & 7) >> 1);
    int reg  = kp >> 3;
    int half = kp & 1;
    int idx = ((((ks * 8 + nt) * 32 + lane) * 2) + reg) * 2 + half;
    g_pBf[idx] = *(unsigned short*)&hv;

    __shared__ float red[DIM];
    red[d] = vrec * vrec;   // pnorm from fp16-reconstructed proto
    __syncthreads();
#pragma unroll
    for (int s = 64; s > 0; s >>= 1) {
        if (d < s) red[d] += red[d + s];
        __syncthreads();
    }
    if (d == 0) g_pnorm[c] = red[0];
}

// ================= kernel 3: fp16 mma GEMM + softmax, 2 M-tiles/warp =====
// 256 threads / 8 warps; warp w owns rows [32w, 32w+32) = 2 M-tiles.
__global__ __launch_bounds__(256, 2) void k_mma(const float* __restrict__ q,
                                                float* __restrict__ out, int nq) {
    extern __shared__ char smem[];
    const uint32_t sb = smem_u32(smem);
    const int tid = threadIdx.x;
    const int wid = tid >> 5, lane = tid & 31;
    const int q0 = blockIdx.x * QT;

    // ---- stage A: warp stages its own 32 rows (fp32 -> fp16, swizzled) ----
#pragma unroll 4
    for (int it = 0; it < 32; it++) {
        int r = wid * 32 + it;
        int qi = q0 + r;
        float4 v = (qi < nq) ? *(const float4*)&q[(size_t)qi * DIM + 4 * lane]
                             : make_float4(0.f, 0.f, 0.f, 0.f);
        __half2 h01 = __float22half2_rn(make_float2(v.x, v.y));
        __half2 h23 = __float22half2_rn(make_float2(v.z, v.w));
        uint64_t h64 = (uint64_t)(*(uint32_t*)&h01) | ((uint64_t)(*(uint32_t*)&h23) << 32);

        int col = 4 * lane;
        int chunk = col >> 6;
        uint32_t off = swz((uint32_t)(r * 128 + (col & 63) * 2));
        *(uint64_t*)(smem + SM_A + chunk * 32768 + off) = h64;

        float s = fmaf(v.x, v.x, fmaf(v.y, v.y, fmaf(v.z, v.z, v.w * v.w)));
#pragma unroll
        for (int o = 16; o > 0; o >>= 1) s += __shfl_xor_sync(0xffffffffu, s, o);
        if (lane == 0) *(float*)(smem + SM_QN + r * 4) = s;
    }
    // ---- stage B fragments + pnorm (linear copies) ----
    {
        const float4* sh4 = (const float4*)g_pBf;
        float4* dh = (float4*)(smem + SM_B);
        dh[tid] = sh4[tid];
        dh[tid + 256] = sh4[tid + 256];
        dh[tid + 512] = sh4[tid + 512];
        dh[tid + 768] = sh4[tid + 768];
        if (tid < N_CLASSES) *(float*)(smem + SM_PN + tid * 4) = g_pnorm[tid];
    }
    __syncthreads();

    // ---- mma mainloop: single fp16 pass, 8 ksteps, 2 M-tiles ----
    float acc0[8][4], acc1[8][4];
#pragma unroll
    for (int nt = 0; nt < 8; nt++)
#pragma unroll
        for (int j = 0; j < 4; j++) { acc0[nt][j] = 0.0f; acc1[nt][j] = 0.0f; }

    const int mrow = wid * 32 + (lane & 7) + ((lane >> 3) & 1) * 8;
    const int koff = (lane >> 4) * 16;

#pragma unroll
    for (int ks = 0; ks < 8; ks++) {
        const int chunk = ks >> 2;
        const int kb = (ks & 3) * 32 + koff;
        uint32_t a0[4], a1[4];
        uint32_t abase = sb + SM_A + chunk * 32768;
        ldmatrix_x4(a0, abase + swz((uint32_t)(mrow * 128 + kb)));
        ldmatrix_x4(a1, abase + swz((uint32_t)((mrow + 16) * 128 + kb)));
        uint2 b[8];
#pragma unroll
        for (int nt = 0; nt < 8; nt++)
            b[nt] = *(const uint2*)(smem + SM_B + ((ks * 8 + nt) * 32 + lane) * 8);
#pragma unroll
        for (int nt = 0; nt < 8; nt++) {
            mma_f16(acc0[nt], a0, b[nt].x, b[nt].y);
            mma_f16(acc1[nt], a1, b[nt].x, b[nt].y);
        }
    }

    // ---- epilogue: dist -> exp -> softmax (4 rows per thread) ----
    const float* s_pn = (const float*)(smem + SM_PN);
    const float* s_qn = (const float*)(smem + SM_QN);
    const int rl = wid * 32 + (lane >> 2);
    float qn0 = s_qn[rl],      qn1 = s_qn[rl + 8];
    float qn2 = s_qn[rl + 16], qn3 = s_qn[rl + 24];
    float s0 = 0.f, s1 = 0.f, s2 = 0.f, s3 = 0.f;
#pragma unroll
    for (int nt = 0; nt < 8; nt++) {
        int c0 = nt * 8 + (lane & 3) * 2;
        float pn0 = s_pn[c0], pn1 = s_pn[c0 + 1];
        float e;
        e = __expf(-sqrtf(fmaxf(fmaf(-2.f, acc0[nt][0], qn0 + pn0), 0.f))); s0 += e; acc0[nt][0] = e;
        e = __expf(-sqrtf(fmaxf(fmaf(-2.f, acc0[nt][1], qn0 + pn1), 0.f))); s0 += e; acc0[nt][1] = e;
        e = __expf(-sqrtf(fmaxf(fmaf(-2.f, acc0[nt][2], qn1 + pn0), 0.f))); s1 += e; acc0[nt][2] = e;
        e = __expf(-sqrtf(fmaxf(fmaf(-2.f, acc0[nt][3], qn1 + pn1), 0.f))); s1 += e; acc0[nt][3] = e;
        e = __expf(-sqrtf(fmaxf(fmaf(-2.f, acc1[nt][0], qn2 + pn0), 0.f))); s2 += e; acc1[nt][0] = e;
        e = __expf(-sqrtf(fmaxf(fmaf(-2.f, acc1[nt][1], qn2 + pn1), 0.f))); s2 += e; acc1[nt][1] = e;
        e = __expf(-sqrtf(fmaxf(fmaf(-2.f, acc1[nt][2], qn3 + pn0), 0.f))); s3 += e; acc1[nt][2] = e;
        e = __expf(-sqrtf(fmaxf(fmaf(-2.f, acc1[nt][3], qn3 + pn1), 0.f))); s3 += e; acc1[nt][3] = e;
    }
#pragma unroll
    for (int o = 1; o <= 2; o <<= 1) {
        s0 += __shfl_xor_sync(0xffffffffu, s0, o);
        s1 += __shfl_xor_sync(0xffffffffu, s1, o);
        s2 += __shfl_xor_sync(0xffffffffu, s2, o);
        s3 += __shfl_xor_sync(0xffffffffu, s3, o);
    }
    float i0 = 1.0f / s0, i1 = 1.0f / s1, i2 = 1.0f / s2, i3 = 1.0f / s3;

    __syncthreads();   // all warps done with A/B smem -> reuse as staging
    float* sout = (float*)(smem + SM_A);
#pragma unroll
    for (int nt = 0; nt < 8; nt++) {
        int c0 = nt * 8 + (lane & 3) * 2;
        *(float2*)(sout + rl * OUT_STRIDE + c0) =
            make_float2(acc0[nt][0] * i0, acc0[nt][1] * i0);
        *(float2*)(sout + (rl + 8) * OUT_STRIDE + c0) =
            make_float2(acc0[nt][2] * i1, acc0[nt][3] * i1);
        *(float2*)(sout + (rl + 16) * OUT_STRIDE + c0) =
            make_float2(acc1[nt][0] * i2, acc1[nt][1] * i2);
        *(float2*)(sout + (rl + 24) * OUT_STRIDE + c0) =
            make_float2(acc1[nt][2] * i3, acc1[nt][3] * i3);
    }
    __syncthreads();

    // coalesced float4 store: 256 rows x 16 float4 = 4096 / 256 thr
#pragma unroll
    for (int i = 0; i < 16; i++) {
        int lin = i * 256 + tid;
        int m = lin >> 4, c4 = lin & 15;
        int qi = q0 + m;
        if (qi < nq) {
            float4 v = *(const float4*)(sout + m * OUT_STRIDE + c4 * 4);
            *(float4*)&out[(size_t)qi * N_CLASSES + c4 * 4] = v;
        }
    }
}

// ---------------- launch ----------------
extern "C" void kernel_launch(void* const* d_in, const int* in_sizes, int n_in,
                              void* d_out, int out_size) {
    const float* emb   = (const float*)d_in[0];
    const int*   lbl32 = (const int*)d_in[1];   // int32 or int64, auto-detected
    const float* query = (const float*)d_in[2];
    float*       out   = (float*)d_out;

    const int nsup = in_sizes[1];
    const int nq   = in_sizes[2] / DIM;

    const int acc_smem = (8 * 2048 + 8 * 64) * 4 + 512 * 4;   // 70 KB
    cudaFuncSetAttribute(k_accum, cudaFuncAttributeMaxDynamicSharedMemorySize, acc_smem);
    cudaFuncSetAttribute(k_mma, cudaFuncAttributeMaxDynamicSharedMemorySize, SM_TOTAL);

    k_zero<<<1, 256>>>(lbl32);
    k_accum<<<ACC_BLOCKS, 256, acc_smem>>>(emb, lbl32, nsup);
    k_final<<<N_CLASSES, DIM>>>();
    int mblocks = (nq + QT - 1) / QT;
    k_mma<<<mblocks, 256, SM_TOTAL>>>(query, out, nq);
}

// round 8
// speedup vs baseline: 1.3720x; 1.3720x over previous
#include <cuda_runtime.h>
#include <cuda_fp16.h>
#include <cstdint>

#define N_CLASSES 64
#define DIM 128
#define QT 128            // queries per block in MMA kernel

// ---------------- device scratch ----------------
__device__ float g_psum[N_CLASSES * DIM];
__device__ float g_pcnt[N_CLASSES];
__device__ float g_pnorm[N_CLASSES];
__device__ int   g_lbl_is64;
// prototypes as fp16, pre-packed in mma.m16n8k16 B-FRAGMENT order:
// [8 ksteps][8 ntiles][32 lanes][2 regs][2 halves]
__device__ unsigned short g_pBf[8192];

// ---------------- helpers ----------------
__device__ __forceinline__ uint32_t smem_u32(const void* p) {
    uint32_t a;
    asm("{ .reg .u64 t; cvta.to.shared.u64 t, %1; cvt.u32.u64 %0, t; }"
        : "=r"(a) : "l"(p));
    return a;
}
__device__ __forceinline__ uint32_t swz(uint32_t off) { return off ^ ((off >> 3) & 0x70); }

__device__ __forceinline__ void ldmatrix_x4(uint32_t* r, uint32_t addr) {
    asm volatile("ldmatrix.sync.aligned.m8n8.x4.shared.b16 {%0,%1,%2,%3}, [%4];"
                 : "=r"(r[0]), "=r"(r[1]), "=r"(r[2]), "=r"(r[3]) : "r"(addr));
}
__device__ __forceinline__ void mma_f16(float* d, const uint32_t* a, uint32_t b0, uint32_t b1) {
    asm volatile(
        "mma.sync.aligned.m16n8k16.row.col.f32.f16.f16.f32 "
        "{%0,%1,%2,%3}, {%4,%5,%6,%7}, {%8,%9}, {%0,%1,%2,%3};"
        : "+f"(d[0]), "+f"(d[1]), "+f"(d[2]), "+f"(d[3])
        : "r"(a[0]), "r"(a[1]), "r"(a[2]), "r"(a[3]), "r"(b0), "r"(b1));
}

// ---------------- smem layout for k_mma (bytes) ----------------
#define SM_QN     0                       // 128 x 4
#define SM_PN     512                     // 64 x 4
#define SM_A      1024                    // 2 chunks x 128 rows x 128B = 32768
#define SM_B      (SM_A + 32768)          // 16384 (B fragments)
#define SM_TOTAL  (SM_B + 16384)          // 50176 -> 3 CTA/SM
#define OUT_STRIDE 68                     // floats; staging 128*68*4 = 34816 OK

// ================= kernel 0: zero + label dtype detect =================
__global__ void k_zero(const int* __restrict__ lbl32) {
    int t = threadIdx.x;
    for (int i = t; i < N_CLASSES * DIM; i += 256) g_psum[i] = 0.0f;
    if (t < N_CLASSES) g_pcnt[t] = 0.0f;

    __shared__ int s_or[256];
    s_or[t] = lbl32[2 * t + 1];
    __syncthreads();
    for (int s = 128; s > 0; s >>= 1) {
        if (t < s) s_or[t] |= s_or[t + s];
        __syncthreads();
    }
    if (t == 0) g_lbl_is64 = (s_or[0] == 0) ? 1 : 0;
}

// ================= kernel 1: class-sum accumulate =================
// Private per-warp slabs (no atomics in the loop) + 8-row batching (MLP=8).
// Warp (g = w&3, p = w>>2): dim-group g, row-half p; slab [64 classes][32].
#define ACC_BLOCKS 128
#define ACC_ROWS   512   // rows per block (65536/128)
__global__ __launch_bounds__(256) void k_accum(const float* __restrict__ emb,
                                               const int* __restrict__ lbl32,
                                               int nrows) {
    extern __shared__ float sh[];
    float* s_slab = sh;                          // 8 x 2048 floats = 64 KB
    float* s_cnt  = sh + 8 * 2048;               // 8 x 64
    int*   s_lbl  = (int*)(s_cnt + 8 * 64);      // 512

    const int tid = threadIdx.x;
    const int w = tid >> 5, lane = tid & 31;
    const int g = w & 3, p = w >> 2;
    const int shift = g_lbl_is64;

    for (int i = tid; i < 8 * 2048; i += 256) s_slab[i] = 0.0f;
    for (int i = tid; i < 8 * 64; i += 256) s_cnt[i] = 0.0f;

    const int r0 = blockIdx.x * ACC_ROWS;
    const int nr = min(ACC_ROWS, nrows - r0);
    for (int i = tid; i < nr; i += 256) s_lbl[i] = lbl32[(r0 + i) << shift];
    __syncthreads();

    float* slab = s_slab + w * 2048;
    float* cnt  = s_cnt + w * 64;
    const int half_n = nr >> 1;
    const int base = p * half_n;
    const float* ecol = emb + (size_t)r0 * DIM + g * 32 + lane;

    int i = 0;
    for (; i + 8 <= half_n; i += 8) {
        int   c[8];
        float v[8];
#pragma unroll
        for (int j = 0; j < 8; j++) c[j] = s_lbl[base + i + j];
#pragma unroll
        for (int j = 0; j < 8; j++) v[j] = ecol[(size_t)(base + i + j) * DIM];
#pragma unroll
        for (int j = 0; j < 8; j++) {
            slab[c[j] * 32 + lane] += v[j];
            if (lane == 0 && g == 0) cnt[c[j]] += 1.0f;
        }
    }
    for (; i < half_n; i++) {
        int c = s_lbl[base + i];
        slab[c * 32 + lane] += ecol[(size_t)(base + i) * DIM];
        if (lane == 0 && g == 0) cnt[c] += 1.0f;
    }
    // odd row when nr is odd (parity-0 warps take it)
    if ((nr & 1) && p == 0) {
        int c = s_lbl[nr - 1];
        slab[c * 32 + lane] += ecol[(size_t)(nr - 1) * DIM];
        if (lane == 0 && g == 0) cnt[c] += 1.0f;
    }
    __syncthreads();

    // flush: sum both parities, one global atomic per element
    for (int idx = tid; idx < N_CLASSES * DIM; idx += 256) {
        int c = idx >> 7, d = idx & 127;
        int gg = d >> 5, l = d & 31;
        float v = s_slab[gg * 2048 + c * 32 + l] + s_slab[(gg + 4) * 2048 + c * 32 + l];
        if (v != 0.0f) atomicAdd(&g_psum[idx], v);
    }
    if (tid < N_CLASSES) {
        float cv = s_cnt[tid] + s_cnt[4 * 64 + tid];
        if (cv != 0.0f) atomicAdd(&g_pcnt[tid], cv);
    }
}

// ================= kernel 2: finalize protos -> fp16 B fragments + pnorm ===
__global__ void k_final() {
    const int c = blockIdx.x;
    const int d = threadIdx.x;
    float cn = fmaxf(g_pcnt[c], 1.0f);
    float v = g_psum[c * DIM + d] / cn;

    __half hv = __float2half_rn(v);
    float vrec = __half2float(hv);

    int nt = c >> 3;
    int ks = d >> 4;
    int kp = d & 15;
    int lane = 4 * (c & 7) + ((kp & 7) >> 1);
    int reg  = kp >> 3;
    int half = kp & 1;
    int idx = ((((ks * 8 + nt) * 32 + lane) * 2) + reg) * 2 + half;
    g_pBf[idx] = *(unsigned short*)&hv;

    __shared__ float red[DIM];
    red[d] = vrec * vrec;   // pnorm from fp16-reconstructed proto
    __syncthreads();
#pragma unroll
    for (int s = 64; s > 0; s >>= 1) {
        if (d < s) red[d] += red[d + s];
        __syncthreads();
    }
    if (d == 0) g_pnorm[c] = red[0];
}

// ================= kernel 3: single-pass fp16 mma GEMM + softmax ========
// (R6 winner, unchanged) 256 threads / 8 warps; warp w owns rows [16w,16w+16).
__global__ __launch_bounds__(256, 3) void k_mma(const float* __restrict__ q,
                                                float* __restrict__ out, int nq) {
    extern __shared__ char smem[];
    const uint32_t sb = smem_u32(smem);
    const int tid = threadIdx.x;
    const int wid = tid >> 5, lane = tid & 31;
    const int q0 = blockIdx.x * QT;

    // ---- stage A: warp per row per iter (fp32 -> fp16, SW128 swizzled) ----
#pragma unroll 4
    for (int it = 0; it < 16; it++) {
        int r = it * 8 + wid;
        int qi = q0 + r;
        float4 v = (qi < nq) ? *(const float4*)&q[(size_t)qi * DIM + 4 * lane]
                             : make_float4(0.f, 0.f, 0.f, 0.f);
        __half2 h01 = __float22half2_rn(make_float2(v.x, v.y));
        __half2 h23 = __float22half2_rn(make_float2(v.z, v.w));
        uint64_t h64 = (uint64_t)(*(uint32_t*)&h01) | ((uint64_t)(*(uint32_t*)&h23) << 32);

        int col = 4 * lane;
        int chunk = col >> 6;
        uint32_t off = swz((uint32_t)(r * 128 + (col & 63) * 2));
        *(uint64_t*)(smem + SM_A + chunk * 16384 + off) = h64;

        float s = fmaf(v.x, v.x, fmaf(v.y, v.y, fmaf(v.z, v.z, v.w * v.w)));
#pragma unroll
        for (int o = 16; o > 0; o >>= 1) s += __shfl_xor_sync(0xffffffffu, s, o);
        if (lane == 0) *(float*)(smem + SM_QN + r * 4) = s;
    }
    // ---- stage B fragments + pnorm (linear copies) ----
    {
        const float4* sh4 = (const float4*)g_pBf;
        float4* dh = (float4*)(smem + SM_B);
        dh[tid] = sh4[tid];
        dh[tid + 256] = sh4[tid + 256];
        dh[tid + 512] = sh4[tid + 512];
        dh[tid + 768] = sh4[tid + 768];
        if (tid < N_CLASSES) *(float*)(smem + SM_PN + tid * 4) = g_pnorm[tid];
    }
    __syncthreads();

    // ---- mma mainloop: single fp16 pass, 8 ksteps ----
    float acc[8][4];
#pragma unroll
    for (int nt = 0; nt < 8; nt++)
#pragma unroll
        for (int j = 0; j < 4; j++) acc[nt][j] = 0.0f;

    const int mrow = wid * 16 + (lane & 7) + ((lane >> 3) & 1) * 8;
    const int koff = (lane >> 4) * 16;

#pragma unroll
    for (int ks = 0; ks < 8; ks++) {
        const int chunk = ks >> 2;
        const int kb = (ks & 3) * 32 + koff;
        uint32_t a[4];
        ldmatrix_x4(a, sb + SM_A + chunk * 16384 + swz((uint32_t)(mrow * 128 + kb)));
        uint2 b[8];
#pragma unroll
        for (int nt = 0; nt < 8; nt++)
            b[nt] = *(const uint2*)(smem + SM_B + ((ks * 8 + nt) * 32 + lane) * 8);
#pragma unroll
        for (int nt = 0; nt < 8; nt++)
            mma_f16(acc[nt], a, b[nt].x, b[nt].y);
    }

    // ---- epilogue: dist -> exp -> softmax ----
    const float* s_pn = (const float*)(smem + SM_PN);
    const float* s_qn = (const float*)(smem + SM_QN);
    const int rl = wid * 16 + (lane >> 2);
    float qnl = s_qn[rl], qnh = s_qn[rl + 8];
    float sl = 0.f, sh = 0.f;
#pragma unroll
    for (int nt = 0; nt < 8; nt++) {
        int c0 = nt * 8 + (lane & 3) * 2;
        float pn0 = s_pn[c0], pn1 = s_pn[c0 + 1];
        float t0 = sqrtf(fmaxf(fmaf(-2.f, acc[nt][0], qnl + pn0), 0.f));
        float t1 = sqrtf(fmaxf(fmaf(-2.f, acc[nt][1], qnl + pn1), 0.f));
        float t2 = sqrtf(fmaxf(fmaf(-2.f, acc[nt][2], qnh + pn0), 0.f));
        float t3 = sqrtf(fmaxf(fmaf(-2.f, acc[nt][3], qnh + pn1), 0.f));
        float e0 = __expf(-t0), e1 = __expf(-t1);
        float e2 = __expf(-t2), e3 = __expf(-t3);
        sl += e0 + e1; sh += e2 + e3;
        acc[nt][0] = e0; acc[nt][1] = e1;
        acc[nt][2] = e2; acc[nt][3] = e3;
    }
    sl += __shfl_xor_sync(0xffffffffu, sl, 1);
    sl += __shfl_xor_sync(0xffffffffu, sl, 2);
    sh += __shfl_xor_sync(0xffffffffu, sh, 1);
    sh += __shfl_xor_sync(0xffffffffu, sh, 2);
    float invl = 1.0f / sl, invh = 1.0f / sh;

    __syncthreads();   // all warps done with A/B smem -> reuse as staging
    float* sout = (float*)(smem + SM_A);
#pragma unroll
    for (int nt = 0; nt < 8; nt++) {
        int c0 = nt * 8 + (lane & 3) * 2;
        *(float2*)(sout + rl * OUT_STRIDE + c0) =
            make_float2(acc[nt][0] * invl, acc[nt][1] * invl);
        *(float2*)(sout + (rl + 8) * OUT_STRIDE + c0) =
            make_float2(acc[nt][2] * invh, acc[nt][3] * invh);
    }
    __syncthreads();

    // coalesced float4 store: 128 rows x 16 float4 = 2048 / 256 thr
#pragma unroll
    for (int i = 0; i < 8; i++) {
        int lin = i * 256 + tid;
        int m = lin >> 4, c4 = lin & 15;
        int qi = q0 + m;
        if (qi < nq) {
            float4 v = *(const float4*)(sout + m * OUT_STRIDE + c4 * 4);
            *(float4*)&out[(size_t)qi * N_CLASSES + c4 * 4] = v;
        }
    }
}

// ---------------- launch ----------------
extern "C" void kernel_launch(void* const* d_in, const int* in_sizes, int n_in,
                              void* d_out, int out_size) {
    const float* emb   = (const float*)d_in[0];
    const int*   lbl32 = (const int*)d_in[1];   // int32 or int64, auto-detected
    const float* query = (const float*)d_in[2];
    float*       out   = (float*)d_out;

    const int nsup = in_sizes[1];
    const int nq   = in_sizes[2] / DIM;

    const int acc_smem = (8 * 2048 + 8 * 64) * 4 + 512 * 4;   // ~68 KB
    cudaFuncSetAttribute(k_accum, cudaFuncAttributeMaxDynamicSharedMemorySize, acc_smem);
    cudaFuncSetAttribute(k_mma, cudaFuncAttributeMaxDynamicSharedMemorySize, SM_TOTAL);

    k_zero<<<1, 256>>>(lbl32);
    k_accum<<<ACC_BLOCKS, 256, acc_smem>>>(emb, lbl32, nsup);
    k_final<<<N_CLASSES, DIM>>>();
    int mblocks = (nq + QT - 1) / QT;
    k_mma<<<mblocks, 256, SM_TOTAL>>>(query, out, nq);
}

// round 9
// speedup vs baseline: 1.7586x; 1.2818x over previous
#include <cuda_runtime.h>
#include <cuda_fp16.h>
#include <cstdint>

#define N_CLASSES 64
#define DIM 128
#define QT 128            // queries per block in MMA kernel
#define ACC_BLOCKS 256
#define ACC_ROWS   256    // rows per accumulate block

// ---------------- device scratch ----------------
__device__ float g_part[ACC_BLOCKS * N_CLASSES * DIM];  // per-block partial sums (8 MB)
__device__ float g_cntp[ACC_BLOCKS * N_CLASSES];        // per-block partial counts
__device__ float g_pnorm[N_CLASSES];
// prototypes as fp16, pre-packed in mma.m16n8k16 B-FRAGMENT order:
// [8 ksteps][8 ntiles][32 lanes][2 regs][2 halves]
__device__ unsigned short g_pBf[8192];

// ---------------- helpers ----------------
__device__ __forceinline__ uint32_t smem_u32(const void* p) {
    uint32_t a;
    asm("{ .reg .u64 t; cvta.to.shared.u64 t, %1; cvt.u32.u64 %0, t; }"
        : "=r"(a) : "l"(p));
    return a;
}
__device__ __forceinline__ uint32_t swz(uint32_t off) { return off ^ ((off >> 3) & 0x70); }

__device__ __forceinline__ void ldmatrix_x4(uint32_t* r, uint32_t addr) {
    asm volatile("ldmatrix.sync.aligned.m8n8.x4.shared.b16 {%0,%1,%2,%3}, [%4];"
                 : "=r"(r[0]), "=r"(r[1]), "=r"(r[2]), "=r"(r[3]) : "r"(addr));
}
__device__ __forceinline__ void mma_f16(float* d, const uint32_t* a, uint32_t b0, uint32_t b1) {
    asm volatile(
        "mma.sync.aligned.m16n8k16.row.col.f32.f16.f16.f32 "
        "{%0,%1,%2,%3}, {%4,%5,%6,%7}, {%8,%9}, {%0,%1,%2,%3};"
        : "+f"(d[0]), "+f"(d[1]), "+f"(d[2]), "+f"(d[3])
        : "r"(a[0]), "r"(a[1]), "r"(a[2]), "r"(a[3]), "r"(b0), "r"(b1));
}

// ---------------- smem layout for k_mma (bytes) ----------------
#define SM_QN     0                       // 128 x 4
#define SM_PN     512                     // 64 x 4
#define SM_A      1024                    // 2 chunks x 128 rows x 128B = 32768
#define SM_B      (SM_A + 32768)          // 16384 (B fragments)
#define SM_TOTAL  (SM_B + 16384)          // 50176 -> 3 CTA/SM

// ================= kernel 1: class-sum accumulate =================
// Private per-warp slabs -> per-block global partials. No atomics, no
// pre-zeroing (every slot written every run). Label dtype detected in-block.
// Warp (g = w&3, p = w>>2): dim-group g, row-half p; slab [64 classes][32].
__global__ __launch_bounds__(256) void k_accum(const float* __restrict__ emb,
                                               const int* __restrict__ lbl32,
                                               int nrows) {
    extern __shared__ float sh[];
    float* s_slab = sh;                          // 8 x 2048 floats = 64 KB
    float* s_cnt  = sh + 8 * 2048;               // 8 x 64
    int*   s_lbl  = (int*)(s_cnt + 8 * 64);      // 256
    __shared__ int s_nz;

    const int tid = threadIdx.x;
    const int w = tid >> 5, lane = tid & 31;
    const int g = w & 3, p = w >> 2;

    for (int i = tid; i < 8 * 2048; i += 256) s_slab[i] = 0.0f;
    for (int i = tid; i < 8 * 64; i += 256) s_cnt[i] = 0.0f;
    if (tid == 0) s_nz = 0;
    __syncthreads();

    // label dtype detect: odd int32 words of first 256 labels all zero => int64
    if (lbl32[2 * tid + 1] != 0) atomicOr(&s_nz, 1);
    __syncthreads();
    const int shift = (s_nz == 0) ? 1 : 0;

    const int r0 = blockIdx.x * ACC_ROWS;
    const int nr = min(ACC_ROWS, nrows - r0);
    for (int i = tid; i < nr; i += 256) s_lbl[i] = lbl32[(r0 + i) << shift];
    __syncthreads();

    float* slab = s_slab + w * 2048;
    float* cnt  = s_cnt + w * 64;
    const int half_n = nr >> 1;
    const int base = p * half_n;
    const float* ecol = emb + (size_t)r0 * DIM + g * 32 + lane;

    int i = 0;
    for (; i + 8 <= half_n; i += 8) {
        int   c[8];
        float v[8];
#pragma unroll
        for (int j = 0; j < 8; j++) c[j] = s_lbl[base + i + j];
#pragma unroll
        for (int j = 0; j < 8; j++) v[j] = ecol[(size_t)(base + i + j) * DIM];
#pragma unroll
        for (int j = 0; j < 8; j++) {
            slab[c[j] * 32 + lane] += v[j];
            if (lane == 0 && g == 0) cnt[c[j]] += 1.0f;
        }
    }
    for (; i < half_n; i++) {
        int c = s_lbl[base + i];
        slab[c * 32 + lane] += ecol[(size_t)(base + i) * DIM];
        if (lane == 0 && g == 0) cnt[c] += 1.0f;
    }
    if ((nr & 1) && p == 0) {   // odd tail row
        int c = s_lbl[nr - 1];
        slab[c * 32 + lane] += ecol[(size_t)(nr - 1) * DIM];
        if (lane == 0 && g == 0) cnt[c] += 1.0f;
    }
    __syncthreads();

    // flush: sum both parities -> plain coalesced global stores
    float* part = g_part + (size_t)blockIdx.x * (N_CLASSES * DIM);
    for (int idx = tid; idx < N_CLASSES * DIM; idx += 256) {
        int c = idx >> 7, d = idx & 127;
        int gg = d >> 5, l = d & 31;
        part[idx] = s_slab[gg * 2048 + c * 32 + l] + s_slab[(gg + 4) * 2048 + c * 32 + l];
    }
    if (tid < N_CLASSES)
        g_cntp[blockIdx.x * N_CLASSES + tid] = s_cnt[tid] + s_cnt[4 * 64 + tid];
}

// ================= kernel 2: reduce partials -> fp16 B fragments + pnorm ===
// 64 blocks (class c), 512 threads: thread (d, qtr) sums 64 block-partials.
__global__ __launch_bounds__(512) void k_final() {
    const int c = blockIdx.x;
    const int d = threadIdx.x & 127;
    const int qtr = threadIdx.x >> 7;

    float s = 0.0f;
    {
        const float* src = g_part + (size_t)(qtr * 64) * (N_CLASSES * DIM) + c * DIM + d;
#pragma unroll 8
        for (int b = 0; b < 64; b++) s += src[(size_t)b * (N_CLASSES * DIM)];
    }
    __shared__ float s_ps[4][DIM];
    __shared__ float s_cr[256];
    __shared__ float red[DIM];
    s_ps[qtr][d] = s;

    if (threadIdx.x < 256) {
        s_cr[threadIdx.x] = g_cntp[threadIdx.x * N_CLASSES + c];
    }
    __syncthreads();
    for (int st = 128; st > 0; st >>= 1) {
        if (threadIdx.x < st) s_cr[threadIdx.x] += s_cr[threadIdx.x + st];
        __syncthreads();
    }
    const float cn = fmaxf(s_cr[0], 1.0f);

    if (threadIdx.x < DIM) {
        float v = (s_ps[0][d] + s_ps[1][d] + s_ps[2][d] + s_ps[3][d]) / cn;
        __half hv = __float2half_rn(v);
        float vrec = __half2float(hv);

        int nt = c >> 3;
        int ks = d >> 4;
        int kp = d & 15;
        int lane = 4 * (c & 7) + ((kp & 7) >> 1);
        int reg  = kp >> 3;
        int half = kp & 1;
        int idx = ((((ks * 8 + nt) * 32 + lane) * 2) + reg) * 2 + half;
        g_pBf[idx] = *(unsigned short*)&hv;
        red[d] = vrec * vrec;   // pnorm from fp16-reconstructed proto
    }
    __syncthreads();
#pragma unroll
    for (int st = 64; st > 0; st >>= 1) {
        if (threadIdx.x < st) red[threadIdx.x] += red[threadIdx.x + st];
        __syncthreads();
    }
    if (threadIdx.x == 0) g_pnorm[c] = red[0];
}

// ================= kernel 3: single-pass fp16 mma GEMM + softmax ========
// 256 threads / 8 warps; warp w owns rows [16w, 16w+16). Direct global
// stores in the epilogue (32B-sector aligned float2 per lane-quad).
__global__ __launch_bounds__(256, 3) void k_mma(const float* __restrict__ q,
                                                float* __restrict__ out, int nq) {
    extern __shared__ char smem[];
    const uint32_t sb = smem_u32(smem);
    const int tid = threadIdx.x;
    const int wid = tid >> 5, lane = tid & 31;
    const int q0 = blockIdx.x * QT;

    // ---- stage A: warp per row per iter (fp32 -> fp16, SW128 swizzled) ----
#pragma unroll 8
    for (int it = 0; it < 16; it++) {
        int r = it * 8 + wid;
        int qi = q0 + r;
        float4 v = (qi < nq) ? *(const float4*)&q[(size_t)qi * DIM + 4 * lane]
                             : make_float4(0.f, 0.f, 0.f, 0.f);
        __half2 h01 = __float22half2_rn(make_float2(v.x, v.y));
        __half2 h23 = __float22half2_rn(make_float2(v.z, v.w));
        uint64_t h64 = (uint64_t)(*(uint32_t*)&h01) | ((uint64_t)(*(uint32_t*)&h23) << 32);

        int col = 4 * lane;
        int chunk = col >> 6;
        uint32_t off = swz((uint32_t)(r * 128 + (col & 63) * 2));
        *(uint64_t*)(smem + SM_A + chunk * 16384 + off) = h64;

        float s = fmaf(v.x, v.x, fmaf(v.y, v.y, fmaf(v.z, v.z, v.w * v.w)));
#pragma unroll
        for (int o = 16; o > 0; o >>= 1) s += __shfl_xor_sync(0xffffffffu, s, o);
        if (lane == 0) *(float*)(smem + SM_QN + r * 4) = s;
    }
    // ---- stage B fragments + pnorm (linear copies) ----
    {
        const float4* sh4 = (const float4*)g_pBf;
        float4* dh = (float4*)(smem + SM_B);
        dh[tid] = sh4[tid];
        dh[tid + 256] = sh4[tid + 256];
        dh[tid + 512] = sh4[tid + 512];
        dh[tid + 768] = sh4[tid + 768];
        if (tid < N_CLASSES) *(float*)(smem + SM_PN + tid * 4) = g_pnorm[tid];
    }
    __syncthreads();

    // ---- mma mainloop: single fp16 pass, 8 ksteps ----
    float acc[8][4];
#pragma unroll
    for (int nt = 0; nt < 8; nt++)
#pragma unroll
        for (int j = 0; j < 4; j++) acc[nt][j] = 0.0f;

    const int mrow = wid * 16 + (lane & 7) + ((lane >> 3) & 1) * 8;
    const int koff = (lane >> 4) * 16;

#pragma unroll
    for (int ks = 0; ks < 8; ks++) {
        const int chunk = ks >> 2;
        const int kb = (ks & 3) * 32 + koff;
        uint32_t a[4];
        ldmatrix_x4(a, sb + SM_A + chunk * 16384 + swz((uint32_t)(mrow * 128 + kb)));
        uint2 b[8];
#pragma unroll
        for (int nt = 0; nt < 8; nt++)
            b[nt] = *(const uint2*)(smem + SM_B + ((ks * 8 + nt) * 32 + lane) * 8);
#pragma unroll
        for (int nt = 0; nt < 8; nt++)
            mma_f16(acc[nt], a, b[nt].x, b[nt].y);
    }

    // ---- epilogue: dist -> exp -> softmax, direct global stores ----
    const float* s_pn = (const float*)(smem + SM_PN);
    const float* s_qn = (const float*)(smem + SM_QN);
    const int rl = wid * 16 + (lane >> 2);
    float qnl = s_qn[rl], qnh = s_qn[rl + 8];
    float sl = 0.f, sh = 0.f;
#pragma unroll
    for (int nt = 0; nt < 8; nt++) {
        int c0 = nt * 8 + (lane & 3) * 2;
        float pn0 = s_pn[c0], pn1 = s_pn[c0 + 1];
        float t0 = sqrtf(fmaxf(fmaf(-2.f, acc[nt][0], qnl + pn0), 0.f));
        float t1 = sqrtf(fmaxf(fmaf(-2.f, acc[nt][1], qnl + pn1), 0.f));
        float t2 = sqrtf(fmaxf(fmaf(-2.f, acc[nt][2], qnh + pn0), 0.f));
        float t3 = sqrtf(fmaxf(fmaf(-2.f, acc[nt][3], qnh + pn1), 0.f));
        float e0 = __expf(-t0), e1 = __expf(-t1);
        float e2 = __expf(-t2), e3 = __expf(-t3);
        sl += e0 + e1; sh += e2 + e3;
        acc[nt][0] = e0; acc[nt][1] = e1;
        acc[nt][2] = e2; acc[nt][3] = e3;
    }
    sl += __shfl_xor_sync(0xffffffffu, sl, 1);
    sl += __shfl_xor_sync(0xffffffffu, sl, 2);
    sh += __shfl_xor_sync(0xffffffffu, sh, 1);
    sh += __shfl_xor_sync(0xffffffffu, sh, 2);
    float invl = 1.0f / sl, invh = 1.0f / sh;

    const int row0 = q0 + rl;       // lane-quad writes a full 32B sector per nt
    const bool ok0 = row0 < nq, ok1 = row0 + 8 < nq;
#pragma unroll
    for (int nt = 0; nt < 8; nt++) {
        int c0 = nt * 8 + (lane & 3) * 2;
        if (ok0)
            *(float2*)&out[(size_t)row0 * N_CLASSES + c0] =
                make_float2(acc[nt][0] * invl, acc[nt][1] * invl);
        if (ok1)
            *(float2*)&out[(size_t)(row0 + 8) * N_CLASSES + c0] =
                make_float2(acc[nt][2] * invh, acc[nt][3] * invh);
    }
}

// ---------------- launch ----------------
extern "C" void kernel_launch(void* const* d_in, const int* in_sizes, int n_in,
                              void* d_out, int out_size) {
    const float* emb   = (const float*)d_in[0];
    const int*   lbl32 = (const int*)d_in[1];   // int32 or int64, auto-detected
    const float* query = (const float*)d_in[2];
    float*       out   = (float*)d_out;

    const int nsup = in_sizes[1];
    const int nq   = in_sizes[2] / DIM;

    const int acc_smem = (8 * 2048 + 8 * 64) * 4 + 256 * 4;   // ~67 KB
    cudaFuncSetAttribute(k_accum, cudaFuncAttributeMaxDynamicSharedMemorySize, acc_smem);
    cudaFuncSetAttribute(k_mma, cudaFuncAttributeMaxDynamicSharedMemorySize, SM_TOTAL);

    k_accum<<<ACC_BLOCKS, 256, acc_smem>>>(emb, lbl32, nsup);
    k_final<<<N_CLASSES, 512>>>();
    int mblocks = (nq + QT - 1) / QT;
    k_mma<<<mblocks, 256, SM_TOTAL>>>(query, out, nq);
}

// round 10
// speedup vs baseline: 1.8010x; 1.0241x over previous
#include <cuda_runtime.h>
#include <cuda_fp16.h>
#include <cstdint>

#define N_CLASSES 64
#define DIM 128
#define QT 128            // queries per block in MMA kernel
#define ACC_BLOCKS 256
#define ACC_ROWS   256    // rows per accumulate block

// ---------------- device scratch ----------------
__device__ float g_part[ACC_BLOCKS * N_CLASSES * DIM];  // per-block partial sums (8 MB)
__device__ float g_cntp[ACC_BLOCKS * N_CLASSES];        // per-block partial counts
__device__ float g_pnorm[N_CLASSES];
// prototypes as fp16, pre-packed in mma.m16n8k16 B-FRAGMENT order:
// [8 ksteps][8 ntiles][32 lanes][2 regs][2 halves]
__device__ unsigned short g_pBf[8192];

// ---------------- helpers ----------------
__device__ __forceinline__ uint32_t smem_u32(const void* p) {
    uint32_t a;
    asm("{ .reg .u64 t; cvta.to.shared.u64 t, %1; cvt.u32.u64 %0, t; }"
        : "=r"(a) : "l"(p));
    return a;
}
__device__ __forceinline__ uint32_t swz(uint32_t off) { return off ^ ((off >> 3) & 0x70); }

__device__ __forceinline__ void ldmatrix_x4(uint32_t* r, uint32_t addr) {
    asm volatile("ldmatrix.sync.aligned.m8n8.x4.shared.b16 {%0,%1,%2,%3}, [%4];"
                 : "=r"(r[0]), "=r"(r[1]), "=r"(r[2]), "=r"(r[3]) : "r"(addr));
}
__device__ __forceinline__ void mma_f16(float* d, const uint32_t* a, uint32_t b0, uint32_t b1) {
    asm volatile(
        "mma.sync.aligned.m16n8k16.row.col.f32.f16.f16.f32 "
        "{%0,%1,%2,%3}, {%4,%5,%6,%7}, {%8,%9}, {%0,%1,%2,%3};"
        : "+f"(d[0]), "+f"(d[1]), "+f"(d[2]), "+f"(d[3])
        : "r"(a[0]), "r"(a[1]), "r"(a[2]), "r"(a[3]), "r"(b0), "r"(b1));
}

// ---------------- smem layout for k_mma (bytes) ----------------
#define SM_QN     0                       // 128 x 4
#define SM_PN     512                     // 64 x 4
#define SM_A      1024                    // 2 chunks x 128 rows x 128B = 32768
#define SM_B      (SM_A + 32768)          // 16384 (B fragments)
#define SM_TOTAL  (SM_B + 16384)          // 50176 -> 4 CTA/SM (smem-wise)

// ================= kernel 1: class-sum accumulate (pipelined) =============
// Private per-warp slabs -> per-block global partials. No atomics, no
// pre-zeroing. Software-pipelined 8-row batches: prefetch batch i+1's loads
// before consuming batch i, so DRAM latency overlaps the smem RMW chain.
__global__ __launch_bounds__(256) void k_accum(const float* __restrict__ emb,
                                               const int* __restrict__ lbl32,
                                               int nrows) {
    extern __shared__ float sh[];
    float* s_slab = sh;                          // 8 x 2048 floats = 64 KB
    float* s_cnt  = sh + 8 * 2048;               // 8 x 64
    int*   s_lbl  = (int*)(s_cnt + 8 * 64);      // 256
    __shared__ int s_nz;

    const int tid = threadIdx.x;
    const int w = tid >> 5, lane = tid & 31;
    const int g = w & 3, p = w >> 2;

    for (int i = tid; i < 8 * 2048; i += 256) s_slab[i] = 0.0f;
    for (int i = tid; i < 8 * 64; i += 256) s_cnt[i] = 0.0f;
    if (tid == 0) s_nz = 0;
    __syncthreads();

    // label dtype detect: odd int32 words of first 256 labels all zero => int64
    if (lbl32[2 * tid + 1] != 0) atomicOr(&s_nz, 1);
    __syncthreads();
    const int shift = (s_nz == 0) ? 1 : 0;

    const int r0 = blockIdx.x * ACC_ROWS;
    const int nr = min(ACC_ROWS, nrows - r0);
    for (int i = tid; i < nr; i += 256) s_lbl[i] = lbl32[(r0 + i) << shift];
    __syncthreads();

    float* slab = s_slab + w * 2048;
    float* cnt  = s_cnt + w * 64;
    const int half_n = nr >> 1;
    const int base = p * half_n;
    const float* ecol = emb + (size_t)r0 * DIM + g * 32 + lane;

    int   c[8], cn_[8];
    float v[8], vn_[8];
    const int nfull = half_n & ~7;

    if (nfull > 0) {   // prologue: load batch 0
#pragma unroll
        for (int j = 0; j < 8; j++) c[j] = s_lbl[base + j];
#pragma unroll
        for (int j = 0; j < 8; j++) v[j] = ecol[(size_t)(base + j) * DIM];
    }
    for (int i = 0; i < nfull; i += 8) {
        const bool more = (i + 8) < nfull;
        if (more) {    // prefetch next batch BEFORE consuming current
#pragma unroll
            for (int j = 0; j < 8; j++) cn_[j] = s_lbl[base + i + 8 + j];
#pragma unroll
            for (int j = 0; j < 8; j++) vn_[j] = ecol[(size_t)(base + i + 8 + j) * DIM];
        }
#pragma unroll
        for (int j = 0; j < 8; j++) {
            slab[c[j] * 32 + lane] += v[j];
            if (lane == 0 && g == 0) cnt[c[j]] += 1.0f;
        }
        if (more) {
#pragma unroll
            for (int j = 0; j < 8; j++) { c[j] = cn_[j]; v[j] = vn_[j]; }
        }
    }
    for (int i = nfull; i < half_n; i++) {   // remainder
        int cc = s_lbl[base + i];
        slab[cc * 32 + lane] += ecol[(size_t)(base + i) * DIM];
        if (lane == 0 && g == 0) cnt[cc] += 1.0f;
    }
    if ((nr & 1) && p == 0) {   // odd tail row
        int cc = s_lbl[nr - 1];
        slab[cc * 32 + lane] += ecol[(size_t)(nr - 1) * DIM];
        if (lane == 0 && g == 0) cnt[cc] += 1.0f;
    }
    __syncthreads();

    // flush: sum both parities -> plain coalesced global stores
    float* part = g_part + (size_t)blockIdx.x * (N_CLASSES * DIM);
    for (int idx = tid; idx < N_CLASSES * DIM; idx += 256) {
        int cc = idx >> 7, d = idx & 127;
        int gg = d >> 5, l = d & 31;
        part[idx] = s_slab[gg * 2048 + cc * 32 + l] + s_slab[(gg + 4) * 2048 + cc * 32 + l];
    }
    if (tid < N_CLASSES)
        g_cntp[blockIdx.x * N_CLASSES + tid] = s_cnt[tid] + s_cnt[4 * 64 + tid];
}

// ================= kernel 2: reduce partials -> fp16 B fragments + pnorm ===
// 64 blocks (class c), 512 threads: thread (d, qtr) sums 64 block-partials.
__global__ __launch_bounds__(512) void k_final() {
    const int c = blockIdx.x;
    const int d = threadIdx.x & 127;
    const int qtr = threadIdx.x >> 7;

    float s = 0.0f;
    {
        const float* src = g_part + (size_t)(qtr * 64) * (N_CLASSES * DIM) + c * DIM + d;
#pragma unroll 8
        for (int b = 0; b < 64; b++) s += src[(size_t)b * (N_CLASSES * DIM)];
    }
    __shared__ float s_ps[4][DIM];
    __shared__ float s_cr[256];
    __shared__ float red[DIM];
    s_ps[qtr][d] = s;

    if (threadIdx.x < 256) {
        s_cr[threadIdx.x] = g_cntp[threadIdx.x * N_CLASSES + c];
    }
    __syncthreads();
    for (int st = 128; st > 0; st >>= 1) {
        if (threadIdx.x < st) s_cr[threadIdx.x] += s_cr[threadIdx.x + st];
        __syncthreads();
    }
    const float cn = fmaxf(s_cr[0], 1.0f);

    if (threadIdx.x < DIM) {
        float v = (s_ps[0][d] + s_ps[1][d] + s_ps[2][d] + s_ps[3][d]) / cn;
        __half hv = __float2half_rn(v);
        float vrec = __half2float(hv);

        int nt = c >> 3;
        int ks = d >> 4;
        int kp = d & 15;
        int lane = 4 * (c & 7) + ((kp & 7) >> 1);
        int reg  = kp >> 3;
        int half = kp & 1;
        int idx = ((((ks * 8 + nt) * 32 + lane) * 2) + reg) * 2 + half;
        g_pBf[idx] = *(unsigned short*)&hv;
        red[d] = vrec * vrec;   // pnorm from fp16-reconstructed proto
    }
    __syncthreads();
#pragma unroll
    for (int st = 64; st > 0; st >>= 1) {
        if (threadIdx.x < st) red[threadIdx.x] += red[threadIdx.x + st];
        __syncthreads();
    }
    if (threadIdx.x == 0) g_pnorm[c] = red[0];
}

// ================= kernel 3: single-pass fp16 mma GEMM + softmax ========
// 256 threads / 8 warps; warp w owns rows [16w, 16w+16). Direct global
// stores in the epilogue. 4 CTAs/SM (<=64 regs).
__global__ __launch_bounds__(256, 4) void k_mma(const float* __restrict__ q,
                                                float* __restrict__ out, int nq) {
    extern __shared__ char smem[];
    const uint32_t sb = smem_u32(smem);
    const int tid = threadIdx.x;
    const int wid = tid >> 5, lane = tid & 31;
    const int q0 = blockIdx.x * QT;

    // ---- stage A: warp per row per iter (fp32 -> fp16, SW128 swizzled) ----
#pragma unroll 8
    for (int it = 0; it < 16; it++) {
        int r = it * 8 + wid;
        int qi = q0 + r;
        float4 v = (qi < nq) ? *(const float4*)&q[(size_t)qi * DIM + 4 * lane]
                             : make_float4(0.f, 0.f, 0.f, 0.f);
        __half2 h01 = __float22half2_rn(make_float2(v.x, v.y));
        __half2 h23 = __float22half2_rn(make_float2(v.z, v.w));
        uint64_t h64 = (uint64_t)(*(uint32_t*)&h01) | ((uint64_t)(*(uint32_t*)&h23) << 32);

        int col = 4 * lane;
        int chunk = col >> 6;
        uint32_t off = swz((uint32_t)(r * 128 + (col & 63) * 2));
        *(uint64_t*)(smem + SM_A + chunk * 16384 + off) = h64;

        float s = fmaf(v.x, v.x, fmaf(v.y, v.y, fmaf(v.z, v.z, v.w * v.w)));
#pragma unroll
        for (int o = 16; o > 0; o >>= 1) s += __shfl_xor_sync(0xffffffffu, s, o);
        if (lane == 0) *(float*)(smem + SM_QN + r * 4) = s;
    }
    // ---- stage B fragments + pnorm (linear copies) ----
    {
        const float4* sh4 = (const float4*)g_pBf;
        float4* dh = (float4*)(smem + SM_B);
        dh[tid] = sh4[tid];
        dh[tid + 256] = sh4[tid + 256];
        dh[tid + 512] = sh4[tid + 512];
        dh[tid + 768] = sh4[tid + 768];
        if (tid < N_CLASSES) *(float*)(smem + SM_PN + tid * 4) = g_pnorm[tid];
    }
    __syncthreads();

    // ---- mma mainloop: single fp16 pass, 8 ksteps ----
    float acc[8][4];
#pragma unroll
    for (int nt = 0; nt < 8; nt++)
#pragma unroll
        for (int j = 0; j < 4; j++) acc[nt][j] = 0.0f;

    const int mrow = wid * 16 + (lane & 7) + ((lane >> 3) & 1) * 8;
    const int koff = (lane >> 4) * 16;

#pragma unroll
    for (int ks = 0; ks < 8; ks++) {
        const int chunk = ks >> 2;
        const int kb = (ks & 3) * 32 + koff;
        uint32_t a[4];
        ldmatrix_x4(a, sb + SM_A + chunk * 16384 + swz((uint32_t)(mrow * 128 + kb)));
        uint2 b[8];
#pragma unroll
        for (int nt = 0; nt < 8; nt++)
            b[nt] = *(const uint2*)(smem + SM_B + ((ks * 8 + nt) * 32 + lane) * 8);
#pragma unroll
        for (int nt = 0; nt < 8; nt++)
            mma_f16(acc[nt], a, b[nt].x, b[nt].y);
    }

    // ---- epilogue: dist -> exp -> softmax, direct global stores ----
    const float* s_pn = (const float*)(smem + SM_PN);
    const float* s_qn = (const float*)(smem + SM_QN);
    const int rl = wid * 16 + (lane >> 2);
    float qnl = s_qn[rl], qnh = s_qn[rl + 8];
    float sl = 0.f, sh = 0.f;
#pragma unroll
    for (int nt = 0; nt < 8; nt++) {
        int c0 = nt * 8 + (lane & 3) * 2;
        float pn0 = s_pn[c0], pn1 = s_pn[c0 + 1];
        float t0 = sqrtf(fmaxf(fmaf(-2.f, acc[nt][0], qnl + pn0), 0.f));
        float t1 = sqrtf(fmaxf(fmaf(-2.f, acc[nt][1], qnl + pn1), 0.f));
        float t2 = sqrtf(fmaxf(fmaf(-2.f, acc[nt][2], qnh + pn0), 0.f));
        float t3 = sqrtf(fmaxf(fmaf(-2.f, acc[nt][3], qnh + pn1), 0.f));
        float e0 = __expf(-t0), e1 = __expf(-t1);
        float e2 = __expf(-t2), e3 = __expf(-t3);
        sl += e0 + e1; sh += e2 + e3;
        acc[nt][0] = e0; acc[nt][1] = e1;
        acc[nt][2] = e2; acc[nt][3] = e3;
    }
    sl += __shfl_xor_sync(0xffffffffu, sl, 1);
    sl += __shfl_xor_sync(0xffffffffu, sl, 2);
    sh += __shfl_xor_sync(0xffffffffu, sh, 1);
    sh += __shfl_xor_sync(0xffffffffu, sh, 2);
    float invl = 1.0f / sl, invh = 1.0f / sh;

    const int row0 = q0 + rl;       // lane-quad writes a full 32B sector per nt
    const bool ok0 = row0 < nq, ok1 = row0 + 8 < nq;
#pragma unroll
    for (int nt = 0; nt < 8; nt++) {
        int c0 = nt * 8 + (lane & 3) * 2;
        if (ok0)
            *(float2*)&out[(size_t)row0 * N_CLASSES + c0] =
                make_float2(acc[nt][0] * invl, acc[nt][1] * invl);
        if (ok1)
            *(float2*)&out[(size_t)(row0 + 8) * N_CLASSES + c0] =
                make_float2(acc[nt][2] * invh, acc[nt][3] * invh);
    }
}

// ---------------- launch ----------------
extern "C" void kernel_launch(void* const* d_in, const int* in_sizes, int n_in,
                              void* d_out, int out_size) {
    const float* emb   = (const float*)d_in[0];
    const int*   lbl32 = (const int*)d_in[1];   // int32 or int64, auto-detected
    const float* query = (const float*)d_in[2];
    float*       out   = (float*)d_out;

    const int nsup = in_sizes[1];
    const int nq   = in_sizes[2] / DIM;

    const int acc_smem = (8 * 2048 + 8 * 64) * 4 + 256 * 4;   // ~67 KB
    cudaFuncSetAttribute(k_accum, cudaFuncAttributeMaxDynamicSharedMemorySize, acc_smem);
    cudaFuncSetAttribute(k_mma, cudaFuncAttributeMaxDynamicSharedMemorySize, SM_TOTAL);

    k_accum<<<ACC_BLOCKS, 256, acc_smem>>>(emb, lbl32, nsup);
    k_final<<<N_CLASSES, 512>>>();
    int mblocks = (nq + QT - 1) / QT;
    k_mma<<<mblocks, 256, SM_TOTAL>>>(query, out, nq);
}